// round 2
// baseline (speedup 1.0000x reference)
#include <cuda_runtime.h>

// Problem constants (fixed by dataset)
#define LP   640
#define LC   128
#define NODE 128
#define HID  32
#define PAIR 128
#define TI   80   // i-rows per block in the main kernel (LP/TI = 8 tiles)

// Scratch (no allocations allowed -> __device__ globals)
__device__ float g_p[LP * HID];            // LN+Linear of p_embed  [i][c]
__device__ float g_c[LC * HID];            // LN+Linear of c_embed  [j][e]
__device__ float g_Mt[LC * HID * PAIR];    // Mt[j][c][k] = sum_e W3[k,c,e] * c[j,e]

__device__ __forceinline__ float warp_sum(float v) {
#pragma unroll
    for (int o = 16; o; o >>= 1) v += __shfl_xor_sync(0xffffffffu, v, o);
    return v;
}

// ---------------------------------------------------------------------------
// Kernel A: per-row LayerNorm + Linear(NODE -> HID).
// grid = rows, block = 128 (one thread per NODE element).
// ---------------------------------------------------------------------------
__global__ void ln_linear_kernel(const float* __restrict__ emb,
                                 const float* __restrict__ lnw,
                                 const float* __restrict__ lnb,
                                 const float* __restrict__ W,
                                 const float* __restrict__ bias,
                                 int which)  // 0 -> g_p, 1 -> g_c
{
    int r = blockIdx.x;
    int t = threadIdx.x;
    __shared__ float part1[4], part2[4], s[NODE];

    float x = emb[r * NODE + t];
    float ws = warp_sum(x);
    if ((t & 31) == 0) part1[t >> 5] = ws;
    __syncthreads();
    float mean = (part1[0] + part1[1] + part1[2] + part1[3]) * (1.0f / NODE);
    float d = x - mean;
    float w2 = warp_sum(d * d);
    if ((t & 31) == 0) part2[t >> 5] = w2;
    __syncthreads();
    float var = (part2[0] + part2[1] + part2[2] + part2[3]) * (1.0f / NODE);
    float xn = d * rsqrtf(var + 1e-5f) * lnw[t] + lnb[t];
    s[t] = xn;
    __syncthreads();

    if (t < HID) {
        float acc = bias[t];
        const float* wr = W + t * NODE;
#pragma unroll 8
        for (int n = 0; n < NODE; n++) acc += s[n] * wr[n];
        float* dst = which ? g_c : g_p;
        dst[r * HID + t] = acc;
    }
}

// ---------------------------------------------------------------------------
// Kernel B: Mt[j][c][k] = sum_e W_out[k, c*HID + e] * g_c[j, e]
// grid = (LC/8, HID/8), block = 128 threads (thread = k). Writes coalesced in k.
// ---------------------------------------------------------------------------
__global__ void make_M_kernel(const float* __restrict__ Wout)
{
    int k  = threadIdx.x;          // 0..127
    int j0 = blockIdx.x * 8;
    int c0 = blockIdx.y * 8;

    __shared__ float cs[8][HID];
    for (int idx = k; idx < 8 * HID; idx += 128)
        cs[idx >> 5][idx & 31] = g_c[(j0 + (idx >> 5)) * HID + (idx & 31)];
    __syncthreads();

#pragma unroll
    for (int c = 0; c < 8; c++) {
        float w[HID];
        const float4* wp = (const float4*)(Wout + (size_t)k * (HID * HID) + (c0 + c) * HID);
#pragma unroll
        for (int q = 0; q < 8; q++) {
            float4 v = wp[q];
            w[4*q] = v.x; w[4*q+1] = v.y; w[4*q+2] = v.z; w[4*q+3] = v.w;
        }
#pragma unroll
        for (int jj = 0; jj < 8; jj++) {
            float acc = 0.f;
#pragma unroll
            for (int e = 0; e < HID; e++) acc += w[e] * cs[jj][e];
            g_Mt[(size_t)(j0 + jj) * (HID * PAIR) + (c0 + c) * PAIR + k] = acc;
        }
    }
}

// ---------------------------------------------------------------------------
// packed fp32x2 FMA (Blackwell): d = a*b + c on both lanes, one instruction.
// ---------------------------------------------------------------------------
__device__ __forceinline__ float2 ffma2(float2 a, float2 b, float2 c) {
    float2 d;
    asm("fma.rn.f32x2 %0, %1, %2, %3;"
        : "=l"(reinterpret_cast<unsigned long long&>(d))
        : "l"(reinterpret_cast<const unsigned long long&>(a)),
          "l"(reinterpret_cast<const unsigned long long&>(b)),
          "l"(reinterpret_cast<const unsigned long long&>(c)));
    return d;
}

// ---------------------------------------------------------------------------
// Kernel C (main): out[i,j,k] = (sum_c p[i,c]*Mt[j,c,k] + b_out[k]) * mask
// grid = (LP/TI, LC), block = 64. Thread t owns k-pair (2t, 2t+1):
//   m[c] in registers, p duplicated into both lanes in smem
//   -> inner loop = 1 LDS.64 + 1 FFMA2. Coalesced float2 stores.
// MASKS ARE INT32 (jax bool widened by the harness).
// ---------------------------------------------------------------------------
__global__ void __launch_bounds__(64)
pair_kernel(const float* __restrict__ b_out,
            const int* __restrict__ pmask,
            const int* __restrict__ cmask,
            float* __restrict__ out)
{
    int j  = blockIdx.y;
    int i0 = blockIdx.x * TI;
    int t  = threadIdx.x;  // 0..63

    // Per-thread Mt column pair: 32 x float2 in registers.
    float2 m[HID];
    const float2* Mt2 = (const float2*)(g_Mt + (size_t)j * (HID * PAIR));
#pragma unroll
    for (int c = 0; c < HID; c++) m[c] = Mt2[c * (PAIR / 2) + t];

    __shared__ float2 psd[TI][HID];   // p duplicated into both lanes
    __shared__ float  pm[TI];
    for (int idx = t; idx < TI * HID; idx += 64) {
        int ii = idx >> 5, c = idx & 31;
        float v = g_p[(i0 + ii) * HID + c];
        psd[ii][c] = make_float2(v, v);
    }
    for (int ii = t; ii < TI; ii += 64) pm[ii] = pmask[i0 + ii] ? 1.0f : 0.0f;
    float cm = cmask[j] ? 1.0f : 0.0f;
    __syncthreads();

    float2 b2 = ((const float2*)b_out)[t];
    float2* outp = (float2*)out + (size_t)i0 * (LC * PAIR / 2) + j * (PAIR / 2) + t;

#pragma unroll 4
    for (int ii = 0; ii < TI; ii++) {
        float2 acc = make_float2(0.f, 0.f);
#pragma unroll
        for (int c = 0; c < HID; c++)
            acc = ffma2(m[c], psd[ii][c], acc);
        float s = pm[ii] * cm;
        float2 r = make_float2((acc.x + b2.x) * s, (acc.y + b2.y) * s);
        outp[(size_t)ii * (LC * PAIR / 2)] = r;
    }
}

// ---------------------------------------------------------------------------
// Kernel D: inter_mask appended after the main output (if buffer has room).
// ---------------------------------------------------------------------------
__global__ void mask_kernel(const int* __restrict__ pmask,
                            const int* __restrict__ cmask,
                            float* __restrict__ outm)
{
    int idx = blockIdx.x * 256 + threadIdx.x;
    if (idx < LP * LC) {
        int i = idx >> 7, j = idx & 127;
        outm[idx] = (pmask[i] && cmask[j]) ? 1.0f : 0.0f;
    }
}

extern "C" void kernel_launch(void* const* d_in, const int* in_sizes, int n_in,
                              void* d_out, int out_size)
{
    const float* p_embed = (const float*)d_in[0];
    const float* c_embed = (const float*)d_in[1];
    const int*   p_mask  = (const int*)d_in[2];
    const int*   c_mask  = (const int*)d_in[3];
    const float* ln_p_w  = (const float*)d_in[4];
    const float* ln_p_b  = (const float*)d_in[5];
    const float* ln_c_w  = (const float*)d_in[6];
    const float* ln_c_b  = (const float*)d_in[7];
    const float* W_p     = (const float*)d_in[8];
    const float* b_p     = (const float*)d_in[9];
    const float* W_c     = (const float*)d_in[10];
    const float* b_c     = (const float*)d_in[11];
    const float* W_out   = (const float*)d_in[12];
    const float* b_out   = (const float*)d_in[13];
    float* out = (float*)d_out;

    ln_linear_kernel<<<LP, NODE>>>(p_embed, ln_p_w, ln_p_b, W_p, b_p, 0);
    ln_linear_kernel<<<LC, NODE>>>(c_embed, ln_c_w, ln_c_b, W_c, b_c, 1);

    dim3 gB(LC / 8, HID / 8);
    make_M_kernel<<<gB, 128>>>(W_out);

    dim3 gC(LP / TI, LC);
    pair_kernel<<<gC, 64>>>(b_out, p_mask, c_mask, out);

    long long main_elems = (long long)LP * LC * PAIR;
    if ((long long)out_size >= main_elems + (long long)LP * LC) {
        mask_kernel<<<(LP * LC + 255) / 256, 256>>>(p_mask, c_mask, out + main_elems);
    }
}

// round 4
// speedup vs baseline: 1.1685x; 1.1685x over previous
#include <cuda_runtime.h>

// Problem constants (fixed by dataset)
#define LP   640
#define LC   128
#define NODE 128
#define HID  32
#define PAIR 128
#define TILE_I 64   // i-rows per block in pair kernel

// Scratch (no allocations allowed -> __device__ globals)
__device__ float g_p[LP * HID];            // LN+Linear of p_embed  [i][c]
__device__ float g_c[LC * HID];            // LN+Linear of c_embed  [j][e]
__device__ float g_Mt[LC * PAIR * HID];    // Mt[j][k][c] = sum_e W3[k,c,e] * c[j,e]

__device__ __forceinline__ float warp_sum(float v) {
#pragma unroll
    for (int o = 16; o; o >>= 1) v += __shfl_xor_sync(0xffffffffu, v, o);
    return v;
}

// packed fp32x2 ops (Blackwell)
__device__ __forceinline__ float2 ffma2(float2 a, float2 b, float2 c) {
    float2 d;
    asm("fma.rn.f32x2 %0, %1, %2, %3;"
        : "=l"(reinterpret_cast<unsigned long long&>(d))
        : "l"(reinterpret_cast<const unsigned long long&>(a)),
          "l"(reinterpret_cast<const unsigned long long&>(b)),
          "l"(reinterpret_cast<const unsigned long long&>(c)));
    return d;
}
__device__ __forceinline__ float2 fmul2(float2 a, float2 b) {
    float2 d;
    asm("mul.rn.f32x2 %0, %1, %2;"
        : "=l"(reinterpret_cast<unsigned long long&>(d))
        : "l"(reinterpret_cast<const unsigned long long&>(a)),
          "l"(reinterpret_cast<const unsigned long long&>(b)));
    return d;
}

// ---------------------------------------------------------------------------
// Kernel A (fused): LayerNorm + Linear(NODE->HID) for BOTH p (rows 0..639)
// and c (rows 640..767). grid = LP+LC, block = 128.
// Linear uses all 128 threads: t = part(2b)*32 + h; 4 partial sums reduced in smem.
// ---------------------------------------------------------------------------
__global__ void __launch_bounds__(128)
ln_linear_all(const float* __restrict__ p_embed, const float* __restrict__ c_embed,
              const float* __restrict__ ln_p_w, const float* __restrict__ ln_p_b,
              const float* __restrict__ ln_c_w, const float* __restrict__ ln_c_b,
              const float* __restrict__ W_p,   const float* __restrict__ b_p,
              const float* __restrict__ W_c,   const float* __restrict__ b_c)
{
    int r = blockIdx.x;
    bool isp = (r < LP);
    int rr = isp ? r : r - LP;
    const float* emb  = isp ? (p_embed + (size_t)rr * NODE) : (c_embed + (size_t)rr * NODE);
    const float* lnw  = isp ? ln_p_w : ln_c_w;
    const float* lnb  = isp ? ln_p_b : ln_c_b;
    const float* W    = isp ? W_p : W_c;
    const float* bias = isp ? b_p : b_c;
    float* dst        = (isp ? g_p : g_c) + (size_t)rr * HID;

    int t = threadIdx.x;
    __shared__ float part1[4], part2[4], s[NODE], red[128];

    float x = emb[t];
    float ws = warp_sum(x);
    if ((t & 31) == 0) part1[t >> 5] = ws;
    __syncthreads();
    float mean = (part1[0] + part1[1] + part1[2] + part1[3]) * (1.0f / NODE);
    float d = x - mean;
    float w2 = warp_sum(d * d);
    if ((t & 31) == 0) part2[t >> 5] = w2;
    __syncthreads();
    float var = (part2[0] + part2[1] + part2[2] + part2[3]) * (1.0f / NODE);
    s[t] = d * rsqrtf(var + 1e-5f) * lnw[t] + lnb[t];
    __syncthreads();

    int h = t & 31, part = t >> 5;
    const float* wr = W + (size_t)h * NODE + part * 32;
    const float* sp = s + part * 32;
    float acc = 0.f;
#pragma unroll
    for (int q = 0; q < 32; q++) acc += sp[q] * wr[q];
    red[t] = acc;
    __syncthreads();
    if (t < HID)
        dst[t] = red[t] + red[t + 32] + red[t + 64] + red[t + 96] + bias[t];
}

// ---------------------------------------------------------------------------
// Kernel B: Mt[j][k][c] = sum_e W_out[k, c*HID + e] * g_c[j, e]
// grid = (LC/8, HID/4), block = 128 threads (thread = k).
// Each thread: 4 c x 8 j accumulators, STG.128 per j-row (c-quad contiguous).
// ---------------------------------------------------------------------------
__global__ void __launch_bounds__(128)
make_M_kernel(const float* __restrict__ Wout)
{
    int k  = threadIdx.x;          // 0..127
    int j0 = blockIdx.x * 8;
    int c0 = blockIdx.y * 4;

    __shared__ float cs[8][HID];
    for (int idx = k; idx < 8 * HID; idx += 128)
        cs[idx >> 5][idx & 31] = g_c[(size_t)(j0 + (idx >> 5)) * HID + (idx & 31)];
    __syncthreads();

    float acc[8][4];
#pragma unroll
    for (int jj = 0; jj < 8; jj++)
#pragma unroll
        for (int c = 0; c < 4; c++) acc[jj][c] = 0.f;

#pragma unroll
    for (int c = 0; c < 4; c++) {
        float w[HID];
        const float4* wp = (const float4*)(Wout + (size_t)k * (HID * HID) + (c0 + c) * HID);
#pragma unroll
        for (int q = 0; q < 8; q++) {
            float4 v = wp[q];
            w[4*q] = v.x; w[4*q+1] = v.y; w[4*q+2] = v.z; w[4*q+3] = v.w;
        }
#pragma unroll
        for (int jj = 0; jj < 8; jj++) {
            float a = 0.f;
#pragma unroll
            for (int e = 0; e < HID; e++) a += w[e] * cs[jj][e];
            acc[jj][c] = a;
        }
    }
#pragma unroll
    for (int jj = 0; jj < 8; jj++) {
        float4 v = make_float4(acc[jj][0], acc[jj][1], acc[jj][2], acc[jj][3]);
        *(float4*)(g_Mt + ((size_t)(j0 + jj) * PAIR + k) * HID + c0) = v;
    }
}

// ---------------------------------------------------------------------------
// Kernel C (main): out[i,j,k] = (sum_c p[i,c]*Mt[j,c,k] + b_out[k]) * mask
// grid = (LP/TILE_I, LC), block = 128 (thread = k, scalar).
// FFMA2 lanes pack an i-PAIR; Mt[j][k][c] duplicated into both lanes in regs.
// Inner loop per c: 2 LDS.128 (broadcast, feeds 4 i's) + 4 FFMA2.
// ---------------------------------------------------------------------------
__global__ void __launch_bounds__(128)
pair_kernel(const float* __restrict__ b_out,
            const int* __restrict__ pmask,
            const int* __restrict__ cmask,
            float* __restrict__ out)
{
    int j  = blockIdx.y;
    int i0 = blockIdx.x * TILE_I;
    int k  = threadIdx.x;  // 0..127

    // md[c] = (Mt[j][k][c], Mt[j][k][c])
    float2 md[HID];
    {
        const float4* src = (const float4*)(g_Mt + ((size_t)j * PAIR + k) * HID);
#pragma unroll
        for (int q = 0; q < 8; q++) {
            float4 v = src[q];
            md[4*q+0] = make_float2(v.x, v.x);
            md[4*q+1] = make_float2(v.y, v.y);
            md[4*q+2] = make_float2(v.z, v.z);
            md[4*q+3] = make_float2(v.w, v.w);
        }
    }

    __shared__ float  pT[HID][68];        // pT[c][ii] transposed, padded (272B row, 16B aligned)
    __shared__ float2 pm2[TILE_I / 2];    // (pm[i]*cm, pm[i+1]*cm)

    float cmv = cmask[j] ? 1.0f : 0.0f;
    {
        int c  = threadIdx.x & 31;
        int i4 = threadIdx.x >> 5;
#pragma unroll
        for (int base = 0; base < TILE_I; base += 4) {
            int ii = base + i4;
            pT[c][ii] = g_p[(size_t)(i0 + ii) * HID + c];
        }
    }
    if (k < TILE_I / 2) {
        float a = pmask[i0 + 2*k]     ? cmv : 0.0f;
        float b = pmask[i0 + 2*k + 1] ? cmv : 0.0f;
        pm2[k] = make_float2(a, b);
    }
    __syncthreads();

    float bk = b_out[k];
    float2 binit = make_float2(bk, bk);
    float* outbase = out + (size_t)i0 * (LC * PAIR) + (size_t)j * PAIR + k;

#pragma unroll 1
    for (int ch = 0; ch < TILE_I / 8; ch++) {
        int li = ch * 8;
        float2 acc0 = binit, acc1 = binit, acc2 = binit, acc3 = binit;
#pragma unroll
        for (int c = 0; c < HID; c++) {
            float4 a = *(const float4*)&pT[c][li];
            float4 b = *(const float4*)&pT[c][li + 4];
            acc0 = ffma2(md[c], make_float2(a.x, a.y), acc0);
            acc1 = ffma2(md[c], make_float2(a.z, a.w), acc1);
            acc2 = ffma2(md[c], make_float2(b.x, b.y), acc2);
            acc3 = ffma2(md[c], make_float2(b.z, b.w), acc3);
        }
        float2 s0 = pm2[li/2 + 0], s1 = pm2[li/2 + 1];
        float2 s2 = pm2[li/2 + 2], s3 = pm2[li/2 + 3];
        acc0 = fmul2(acc0, s0);
        acc1 = fmul2(acc1, s1);
        acc2 = fmul2(acc2, s2);
        acc3 = fmul2(acc3, s3);
        outbase[(size_t)(li + 0) * (LC * PAIR)] = acc0.x;
        outbase[(size_t)(li + 1) * (LC * PAIR)] = acc0.y;
        outbase[(size_t)(li + 2) * (LC * PAIR)] = acc1.x;
        outbase[(size_t)(li + 3) * (LC * PAIR)] = acc1.y;
        outbase[(size_t)(li + 4) * (LC * PAIR)] = acc2.x;
        outbase[(size_t)(li + 5) * (LC * PAIR)] = acc2.y;
        outbase[(size_t)(li + 6) * (LC * PAIR)] = acc3.x;
        outbase[(size_t)(li + 7) * (LC * PAIR)] = acc3.y;
    }
}

// ---------------------------------------------------------------------------
// Kernel D: inter_mask appended after the main output (if buffer has room).
// ---------------------------------------------------------------------------
__global__ void mask_kernel(const int* __restrict__ pmask,
                            const int* __restrict__ cmask,
                            float* __restrict__ outm)
{
    int idx = blockIdx.x * 256 + threadIdx.x;
    if (idx < LP * LC) {
        int i = idx >> 7, jj = idx & 127;
        outm[idx] = (pmask[i] && cmask[jj]) ? 1.0f : 0.0f;
    }
}

extern "C" void kernel_launch(void* const* d_in, const int* in_sizes, int n_in,
                              void* d_out, int out_size)
{
    const float* p_embed = (const float*)d_in[0];
    const float* c_embed = (const float*)d_in[1];
    const int*   p_mask  = (const int*)d_in[2];
    const int*   c_mask  = (const int*)d_in[3];
    const float* ln_p_w  = (const float*)d_in[4];
    const float* ln_p_b  = (const float*)d_in[5];
    const float* ln_c_w  = (const float*)d_in[6];
    const float* ln_c_b  = (const float*)d_in[7];
    const float* W_p     = (const float*)d_in[8];
    const float* b_p     = (const float*)d_in[9];
    const float* W_c     = (const float*)d_in[10];
    const float* b_c     = (const float*)d_in[11];
    const float* W_out   = (const float*)d_in[12];
    const float* b_out   = (const float*)d_in[13];
    float* out = (float*)d_out;

    ln_linear_all<<<LP + LC, 128>>>(p_embed, c_embed, ln_p_w, ln_p_b,
                                    ln_c_w, ln_c_b, W_p, b_p, W_c, b_c);

    dim3 gB(LC / 8, HID / 4);
    make_M_kernel<<<gB, 128>>>(W_out);

    dim3 gC(LP / TILE_I, LC);
    pair_kernel<<<gC, 128>>>(b_out, p_mask, c_mask, out);

    long long main_elems = (long long)LP * LC * PAIR;
    if ((long long)out_size >= main_elems + (long long)LP * LC) {
        mask_kernel<<<(LP * LC + 255) / 256, 256>>>(p_mask, c_mask, out + main_elems);
    }
}

// round 5
// speedup vs baseline: 1.8067x; 1.5462x over previous
#include <cuda_runtime.h>

// Problem constants (fixed by dataset)
#define LP   640
#define LC   128
#define NODE 128
#define HID  32
#define PAIR 128
#define TILE_I 64   // i-rows per block in pair kernel
#define JPB  2      // j columns per pair block

// Scratch (no allocations allowed -> __device__ globals)
__device__ float g_p[LP * HID];            // LN+Linear of p_embed  [i][c]
__device__ float g_c[LC * HID];            // LN+Linear of c_embed  [j][e]
__device__ float g_Mt[LC * PAIR * HID];    // Mt[j][k][c] = sum_e W3[k,c,e] * c[j,e]

__device__ __forceinline__ float warp_sum(float v) {
#pragma unroll
    for (int o = 16; o; o >>= 1) v += __shfl_xor_sync(0xffffffffu, v, o);
    return v;
}

// packed fp32x2 ops (Blackwell)
__device__ __forceinline__ float2 ffma2(float2 a, float2 b, float2 c) {
    float2 d;
    asm("fma.rn.f32x2 %0, %1, %2, %3;"
        : "=l"(reinterpret_cast<unsigned long long&>(d))
        : "l"(reinterpret_cast<const unsigned long long&>(a)),
          "l"(reinterpret_cast<const unsigned long long&>(b)),
          "l"(reinterpret_cast<const unsigned long long&>(c)));
    return d;
}
__device__ __forceinline__ float2 fmul2(float2 a, float2 b) {
    float2 d;
    asm("mul.rn.f32x2 %0, %1, %2;"
        : "=l"(reinterpret_cast<unsigned long long&>(d))
        : "l"(reinterpret_cast<const unsigned long long&>(a)),
          "l"(reinterpret_cast<const unsigned long long&>(b)));
    return d;
}

// ---------------------------------------------------------------------------
// Kernel A (fused): LayerNorm + Linear(NODE->HID) for BOTH p (rows 0..639)
// and c (rows 640..767). grid = LP+LC, block = 128.
// ---------------------------------------------------------------------------
__global__ void __launch_bounds__(128)
ln_linear_all(const float* __restrict__ p_embed, const float* __restrict__ c_embed,
              const float* __restrict__ ln_p_w, const float* __restrict__ ln_p_b,
              const float* __restrict__ ln_c_w, const float* __restrict__ ln_c_b,
              const float* __restrict__ W_p,   const float* __restrict__ b_p,
              const float* __restrict__ W_c,   const float* __restrict__ b_c)
{
    int r = blockIdx.x;
    bool isp = (r < LP);
    int rr = isp ? r : r - LP;
    const float* emb  = isp ? (p_embed + (size_t)rr * NODE) : (c_embed + (size_t)rr * NODE);
    const float* lnw  = isp ? ln_p_w : ln_c_w;
    const float* lnb  = isp ? ln_p_b : ln_c_b;
    const float* W    = isp ? W_p : W_c;
    const float* bias = isp ? b_p : b_c;
    float* dst        = (isp ? g_p : g_c) + (size_t)rr * HID;

    int t = threadIdx.x;
    __shared__ float part1[4], part2[4], s[NODE], red[128];

    float x = emb[t];
    float ws = warp_sum(x);
    if ((t & 31) == 0) part1[t >> 5] = ws;
    __syncthreads();
    float mean = (part1[0] + part1[1] + part1[2] + part1[3]) * (1.0f / NODE);
    float d = x - mean;
    float w2 = warp_sum(d * d);
    if ((t & 31) == 0) part2[t >> 5] = w2;
    __syncthreads();
    float var = (part2[0] + part2[1] + part2[2] + part2[3]) * (1.0f / NODE);
    s[t] = d * rsqrtf(var + 1e-5f) * lnw[t] + lnb[t];
    __syncthreads();

    int h = t & 31, part = t >> 5;
    const float* wr = W + (size_t)h * NODE + part * 32;
    const float* sp = s + part * 32;
    float acc = 0.f;
#pragma unroll
    for (int q = 0; q < 32; q++) acc += sp[q] * wr[q];
    red[t] = acc;
    __syncthreads();
    if (t < HID)
        dst[t] = red[t] + red[t + 32] + red[t + 64] + red[t + 96] + bias[t];
}

// ---------------------------------------------------------------------------
// Kernel B: Mt[j][k][c] = sum_e W_out[k, c*HID + e] * g_c[j, e]
// grid = (LC/8, HID/4), block = 128 threads (thread = k).
// ---------------------------------------------------------------------------
__global__ void __launch_bounds__(128)
make_M_kernel(const float* __restrict__ Wout)
{
    int k  = threadIdx.x;          // 0..127
    int j0 = blockIdx.x * 8;
    int c0 = blockIdx.y * 4;

    __shared__ float cs[8][HID];
    for (int idx = k; idx < 8 * HID; idx += 128)
        cs[idx >> 5][idx & 31] = g_c[(size_t)(j0 + (idx >> 5)) * HID + (idx & 31)];
    __syncthreads();

    float acc[8][4];
#pragma unroll
    for (int c = 0; c < 4; c++) {
        float w[HID];
        const float4* wp = (const float4*)(Wout + (size_t)k * (HID * HID) + (c0 + c) * HID);
#pragma unroll
        for (int q = 0; q < 8; q++) {
            float4 v = wp[q];
            w[4*q] = v.x; w[4*q+1] = v.y; w[4*q+2] = v.z; w[4*q+3] = v.w;
        }
#pragma unroll
        for (int jj = 0; jj < 8; jj++) {
            float a = 0.f;
#pragma unroll
            for (int e = 0; e < HID; e++) a += w[e] * cs[jj][e];
            acc[jj][c] = a;
        }
    }
#pragma unroll
    for (int jj = 0; jj < 8; jj++) {
        float4 v = make_float4(acc[jj][0], acc[jj][1], acc[jj][2], acc[jj][3]);
        *(float4*)(g_Mt + ((size_t)(j0 + jj) * PAIR + k) * HID + c0) = v;
    }
}

// ---------------------------------------------------------------------------
// Kernel C (main): out[i,j,k] = (sum_c p[i,c]*Mt[j,c,k] + b_out[k]) * mask
// grid = (LP/TILE_I, LC/JPB), block = 256.
// Thread: jl = tid>>7 (which of 2 j's), k = tid&127.
// FFMA2 lanes pack an i-PAIR; Mt[j][k][c] duplicated into both lanes in regs.
// Both j-halves share one pT smem tile. Also writes the appended inter_mask
// region (640 blocks x 128 entries covers LP*LC exactly).
// ---------------------------------------------------------------------------
__global__ void __launch_bounds__(256)
pair_kernel(const float* __restrict__ b_out,
            const int* __restrict__ pmask,
            const int* __restrict__ cmask,
            float* __restrict__ out,
            float* __restrict__ outm,   // mask region or nullptr
            int has_mask)
{
    int tid = threadIdx.x;
    int jl  = tid >> 7;                 // 0..1
    int k   = tid & 127;                // 0..127
    int j   = blockIdx.y * JPB + jl;
    int i0  = blockIdx.x * TILE_I;

    // md[c] = (Mt[j][k][c], Mt[j][k][c])
    float2 md[HID];
    {
        const float4* src = (const float4*)(g_Mt + ((size_t)j * PAIR + k) * HID);
#pragma unroll
        for (int q = 0; q < 8; q++) {
            float4 v = src[q];
            md[4*q+0] = make_float2(v.x, v.x);
            md[4*q+1] = make_float2(v.y, v.y);
            md[4*q+2] = make_float2(v.z, v.z);
            md[4*q+3] = make_float2(v.w, v.w);
        }
    }

    __shared__ float  pT[HID][68];          // pT[c][ii], padded rows (272B)
    __shared__ float2 pmc[JPB][TILE_I / 2]; // (pm[i]*cm_j, pm[i+1]*cm_j)

    // fill pT: 256 threads, c = tid&31, i-group = tid>>5 (8 groups)
    {
        int c  = tid & 31;
        int ig = tid >> 5;
#pragma unroll
        for (int base = 0; base < TILE_I; base += 8) {
            int ii = base + ig;
            pT[c][ii] = g_p[(size_t)(i0 + ii) * HID + c];
        }
    }
    if (tid < JPB * (TILE_I / 2)) {
        int jl2 = tid / (TILE_I / 2);
        int t   = tid % (TILE_I / 2);
        float cm = cmask[blockIdx.y * JPB + jl2] ? 1.0f : 0.0f;
        float a = pmask[i0 + 2*t]     ? cm : 0.0f;
        float b = pmask[i0 + 2*t + 1] ? cm : 0.0f;
        pmc[jl2][t] = make_float2(a, b);
    }
    // appended inter_mask: 640 blocks x 128 entries = LP*LC
    if (has_mask && jl == 0) {
        int bl  = blockIdx.y * gridDim.x + blockIdx.x;   // 0..639
        int idx = bl * 128 + k;
        int im  = idx >> 7, jm = idx & 127;
        outm[idx] = (pmask[im] && cmask[jm]) ? 1.0f : 0.0f;
    }
    __syncthreads();

    float bk = b_out[k];
    float2 binit = make_float2(bk, bk);
    float* outbase = out + (size_t)i0 * (LC * PAIR) + (size_t)j * PAIR + k;

#pragma unroll 1
    for (int ch = 0; ch < TILE_I / 8; ch++) {
        int li = ch * 8;
        float2 acc0 = binit, acc1 = binit, acc2 = binit, acc3 = binit;
#pragma unroll
        for (int c = 0; c < HID; c++) {
            float4 a = *(const float4*)&pT[c][li];
            float4 b = *(const float4*)&pT[c][li + 4];
            acc0 = ffma2(md[c], make_float2(a.x, a.y), acc0);
            acc1 = ffma2(md[c], make_float2(a.z, a.w), acc1);
            acc2 = ffma2(md[c], make_float2(b.x, b.y), acc2);
            acc3 = ffma2(md[c], make_float2(b.z, b.w), acc3);
        }
        acc0 = fmul2(acc0, pmc[jl][li/2 + 0]);
        acc1 = fmul2(acc1, pmc[jl][li/2 + 1]);
        acc2 = fmul2(acc2, pmc[jl][li/2 + 2]);
        acc3 = fmul2(acc3, pmc[jl][li/2 + 3]);
        outbase[(size_t)(li + 0) * (LC * PAIR)] = acc0.x;
        outbase[(size_t)(li + 1) * (LC * PAIR)] = acc0.y;
        outbase[(size_t)(li + 2) * (LC * PAIR)] = acc1.x;
        outbase[(size_t)(li + 3) * (LC * PAIR)] = acc1.y;
        outbase[(size_t)(li + 4) * (LC * PAIR)] = acc2.x;
        outbase[(size_t)(li + 5) * (LC * PAIR)] = acc2.y;
        outbase[(size_t)(li + 6) * (LC * PAIR)] = acc3.x;
        outbase[(size_t)(li + 7) * (LC * PAIR)] = acc3.y;
    }
}

extern "C" void kernel_launch(void* const* d_in, const int* in_sizes, int n_in,
                              void* d_out, int out_size)
{
    const float* p_embed = (const float*)d_in[0];
    const float* c_embed = (const float*)d_in[1];
    const int*   p_mask  = (const int*)d_in[2];
    const int*   c_mask  = (const int*)d_in[3];
    const float* ln_p_w  = (const float*)d_in[4];
    const float* ln_p_b  = (const float*)d_in[5];
    const float* ln_c_w  = (const float*)d_in[6];
    const float* ln_c_b  = (const float*)d_in[7];
    const float* W_p     = (const float*)d_in[8];
    const float* b_p     = (const float*)d_in[9];
    const float* W_c     = (const float*)d_in[10];
    const float* b_c     = (const float*)d_in[11];
    const float* W_out   = (const float*)d_in[12];
    const float* b_out   = (const float*)d_in[13];
    float* out = (float*)d_out;

    ln_linear_all<<<LP + LC, 128>>>(p_embed, c_embed, ln_p_w, ln_p_b,
                                    ln_c_w, ln_c_b, W_p, b_p, W_c, b_c);

    dim3 gB(LC / 8, HID / 4);
    make_M_kernel<<<gB, 128>>>(W_out);

    long long main_elems = (long long)LP * LC * PAIR;
    int has_mask = ((long long)out_size >= main_elems + (long long)LP * LC) ? 1 : 0;
    float* outm = out + main_elems;

    dim3 gC(LP / TILE_I, LC / JPB);
    pair_kernel<<<gC, 256>>>(b_out, p_mask, c_mask, out, outm, has_mask);
}

// round 7
// speedup vs baseline: 2.3225x; 1.2855x over previous
#include <cuda_runtime.h>

// Problem constants (fixed by dataset)
#define LP   640
#define LC   128
#define NODE 128
#define HID  32
#define PAIR 128
#define TILE_I 64   // i-rows per block in pair kernel
#define JPB  2      // j columns per pair block

// Scratch (no allocations allowed -> __device__ globals)
__device__ float g_p[LP * HID];            // LN+Linear of p_embed  [i][c]
__device__ float g_c[LC * HID];            // LN+Linear of c_embed  [j][e]
__device__ float g_Mt[LC * PAIR * HID];    // Mt[j][k][c] = sum_e W3[k,c,e] * c[j,e]

__device__ __forceinline__ float warp_sum(float v) {
#pragma unroll
    for (int o = 16; o; o >>= 1) v += __shfl_xor_sync(0xffffffffu, v, o);
    return v;
}

// packed fp32x2 ops (Blackwell)
__device__ __forceinline__ float2 ffma2(float2 a, float2 b, float2 c) {
    float2 d;
    asm("fma.rn.f32x2 %0, %1, %2, %3;"
        : "=l"(reinterpret_cast<unsigned long long&>(d))
        : "l"(reinterpret_cast<const unsigned long long&>(a)),
          "l"(reinterpret_cast<const unsigned long long&>(b)),
          "l"(reinterpret_cast<const unsigned long long&>(c)));
    return d;
}
__device__ __forceinline__ float2 fmul2(float2 a, float2 b) {
    float2 d;
    asm("mul.rn.f32x2 %0, %1, %2;"
        : "=l"(reinterpret_cast<unsigned long long&>(d))
        : "l"(reinterpret_cast<const unsigned long long&>(a)),
          "l"(reinterpret_cast<const unsigned long long&>(b)));
    return d;
}

// ---------------------------------------------------------------------------
// Kernel A (fused): LayerNorm + Linear(NODE->HID) for BOTH p (rows 0..639)
// and c (rows 640..767). grid = LP+LC, block = 128.
// Linear phase: warp w computes h = 8w..8w+7; lane loads float4 of W row
// (COALESCED 512B per warp) + float4 of s; 4 FMA + warp reduction per h.
// ---------------------------------------------------------------------------
__global__ void __launch_bounds__(128)
ln_linear_all(const float* __restrict__ p_embed, const float* __restrict__ c_embed,
              const float* __restrict__ ln_p_w, const float* __restrict__ ln_p_b,
              const float* __restrict__ ln_c_w, const float* __restrict__ ln_c_b,
              const float* __restrict__ W_p,   const float* __restrict__ b_p,
              const float* __restrict__ W_c,   const float* __restrict__ b_c)
{
    int r = blockIdx.x;
    bool isp = (r < LP);
    int rr = isp ? r : r - LP;
    const float* emb  = isp ? (p_embed + (size_t)rr * NODE) : (c_embed + (size_t)rr * NODE);
    const float* lnw  = isp ? ln_p_w : ln_c_w;
    const float* lnb  = isp ? ln_p_b : ln_c_b;
    const float* W    = isp ? W_p : W_c;
    const float* bias = isp ? b_p : b_c;
    float* dst        = (isp ? g_p : g_c) + (size_t)rr * HID;

    int t = threadIdx.x;
    __shared__ float part1[4], part2[4];
    __shared__ __align__(16) float s[NODE];

    float x = emb[t];
    float ws = warp_sum(x);
    if ((t & 31) == 0) part1[t >> 5] = ws;
    __syncthreads();
    float mean = (part1[0] + part1[1] + part1[2] + part1[3]) * (1.0f / NODE);
    float d = x - mean;
    float w2 = warp_sum(d * d);
    if ((t & 31) == 0) part2[t >> 5] = w2;
    __syncthreads();
    float var = (part2[0] + part2[1] + part2[2] + part2[3]) * (1.0f / NODE);
    s[t] = d * rsqrtf(var + 1e-5f) * lnw[t] + lnb[t];
    __syncthreads();

    int w = t >> 5, lane = t & 31;
    float4 sv = ((const float4*)s)[lane];
#pragma unroll
    for (int rrh = 0; rrh < 8; rrh++) {
        int h = w * 8 + rrh;
        float4 wv = ((const float4*)(W + (size_t)h * NODE))[lane];
        float a = wv.x * sv.x + wv.y * sv.y + wv.z * sv.z + wv.w * sv.w;
        a = warp_sum(a);
        if (lane == 0) dst[h] = a + bias[h];
    }
}

// ---------------------------------------------------------------------------
// Kernel B: Mt[j][k][c] = sum_e W_out[k, c*HID + e] * g_c[j, e]
// grid = (LC/8, HID/2), block = 128 (thread = k). W_out slice (128 k x 64
// floats) staged through smem COALESCED; padded rows [67] -> conflict-free
// compute reads (bank stride 3). float2 stores, 8B aligned.
// ---------------------------------------------------------------------------
__global__ void __launch_bounds__(128)
make_M_kernel(const float* __restrict__ Wout)
{
    int k  = threadIdx.x;          // 0..127
    int j0 = blockIdx.x * 8;
    int cb = blockIdx.y;           // c-pair index: global c = cb*2 + {0,1}

    __shared__ float ws[128][67];  // ws[k][c*32+e], padded
    __shared__ float cs[8][HID];

    // Stage W_out slice coalesced: gmem float offset = kk*1024 + cb*64 + x (x<64)
    {
        const float* base = Wout + (size_t)cb * 64;
#pragma unroll
        for (int q = 0; q < 16; q++) {
            int lin4 = q * 128 + k;        // 0..2047 float4s
            int kk   = lin4 >> 4;          // 16 float4 per k
            int x4   = lin4 & 15;
            float4 v = *(const float4*)(base + (size_t)kk * 1024 + x4 * 4);
            ws[kk][x4 * 4 + 0] = v.x;
            ws[kk][x4 * 4 + 1] = v.y;
            ws[kk][x4 * 4 + 2] = v.z;
            ws[kk][x4 * 4 + 3] = v.w;
        }
    }
    for (int idx = k; idx < 8 * HID; idx += 128)
        cs[idx >> 5][idx & 31] = g_c[(size_t)(j0 + (idx >> 5)) * HID + (idx & 31)];
    __syncthreads();

    float acc[8][2];
#pragma unroll
    for (int jj = 0; jj < 8; jj++) { acc[jj][0] = 0.f; acc[jj][1] = 0.f; }

#pragma unroll
    for (int e = 0; e < HID; e++) {
        float w0 = ws[k][e];
        float w1 = ws[k][32 + e];
#pragma unroll
        for (int jj = 0; jj < 8; jj++) {
            float ce = cs[jj][e];
            acc[jj][0] += w0 * ce;
            acc[jj][1] += w1 * ce;
        }
    }
#pragma unroll
    for (int jj = 0; jj < 8; jj++) {
        float2 v = make_float2(acc[jj][0], acc[jj][1]);
        *(float2*)(g_Mt + ((size_t)(j0 + jj) * PAIR + k) * HID + cb * 2) = v;
    }
}

// ---------------------------------------------------------------------------
// Kernel C (main): out[i,j,k] = (sum_c p[i,c]*Mt[j,c,k] + b_out[k]) * mask
// grid = (LP/TILE_I, LC/JPB), block = 256.
// ---------------------------------------------------------------------------
__global__ void __launch_bounds__(256)
pair_kernel(const float* __restrict__ b_out,
            const int* __restrict__ pmask,
            const int* __restrict__ cmask,
            float* __restrict__ out,
            float* __restrict__ outm,   // mask region or nullptr
            int has_mask)
{
    int tid = threadIdx.x;
    int jl  = tid >> 7;                 // 0..1
    int k   = tid & 127;                // 0..127
    int j   = blockIdx.y * JPB + jl;
    int i0  = blockIdx.x * TILE_I;

    // md[c] = (Mt[j][k][c], Mt[j][k][c])
    float2 md[HID];
    {
        const float4* src = (const float4*)(g_Mt + ((size_t)j * PAIR + k) * HID);
#pragma unroll
        for (int q = 0; q < 8; q++) {
            float4 v = src[q];
            md[4*q+0] = make_float2(v.x, v.x);
            md[4*q+1] = make_float2(v.y, v.y);
            md[4*q+2] = make_float2(v.z, v.z);
            md[4*q+3] = make_float2(v.w, v.w);
        }
    }

    __shared__ float  pT[HID][68];          // pT[c][ii], padded rows (272B)
    __shared__ float2 pmc[JPB][TILE_I / 2]; // (pm[i]*cm_j, pm[i+1]*cm_j)

    {
        int c  = tid & 31;
        int ig = tid >> 5;
#pragma unroll
        for (int base = 0; base < TILE_I; base += 8) {
            int ii = base + ig;
            pT[c][ii] = g_p[(size_t)(i0 + ii) * HID + c];
        }
    }
    if (tid < JPB * (TILE_I / 2)) {
        int jl2 = tid / (TILE_I / 2);
        int t   = tid % (TILE_I / 2);
        float cm = cmask[blockIdx.y * JPB + jl2] ? 1.0f : 0.0f;
        float a = pmask[i0 + 2*t]     ? cm : 0.0f;
        float b = pmask[i0 + 2*t + 1] ? cm : 0.0f;
        pmc[jl2][t] = make_float2(a, b);
    }
    // appended inter_mask: 640 blocks x 128 entries = LP*LC
    if (has_mask && jl == 0) {
        int bl  = blockIdx.y * gridDim.x + blockIdx.x;   // 0..639
        int idx = bl * 128 + k;
        int im  = idx >> 7, jm = idx & 127;
        outm[idx] = (pmask[im] && cmask[jm]) ? 1.0f : 0.0f;
    }
    __syncthreads();

    float bk = b_out[k];
    float2 binit = make_float2(bk, bk);
    float* outbase = out + (size_t)i0 * (LC * PAIR) + (size_t)j * PAIR + k;

#pragma unroll 1
    for (int ch = 0; ch < TILE_I / 8; ch++) {
        int li = ch * 8;
        float2 acc0 = binit, acc1 = binit, acc2 = binit, acc3 = binit;
#pragma unroll
        for (int c = 0; c < HID; c++) {
            float4 a = *(const float4*)&pT[c][li];
            float4 b = *(const float4*)&pT[c][li + 4];
            acc0 = ffma2(md[c], make_float2(a.x, a.y), acc0);
            acc1 = ffma2(md[c], make_float2(a.z, a.w), acc1);
            acc2 = ffma2(md[c], make_float2(b.x, b.y), acc2);
            acc3 = ffma2(md[c], make_float2(b.z, b.w), acc3);
        }
        acc0 = fmul2(acc0, pmc[jl][li/2 + 0]);
        acc1 = fmul2(acc1, pmc[jl][li/2 + 1]);
        acc2 = fmul2(acc2, pmc[jl][li/2 + 2]);
        acc3 = fmul2(acc3, pmc[jl][li/2 + 3]);
        outbase[(size_t)(li + 0) * (LC * PAIR)] = acc0.x;
        outbase[(size_t)(li + 1) * (LC * PAIR)] = acc0.y;
        outbase[(size_t)(li + 2) * (LC * PAIR)] = acc1.x;
        outbase[(size_t)(li + 3) * (LC * PAIR)] = acc1.y;
        outbase[(size_t)(li + 4) * (LC * PAIR)] = acc2.x;
        outbase[(size_t)(li + 5) * (LC * PAIR)] = acc2.y;
        outbase[(size_t)(li + 6) * (LC * PAIR)] = acc3.x;
        outbase[(size_t)(li + 7) * (LC * PAIR)] = acc3.y;
    }
}

extern "C" void kernel_launch(void* const* d_in, const int* in_sizes, int n_in,
                              void* d_out, int out_size)
{
    const float* p_embed = (const float*)d_in[0];
    const float* c_embed = (const float*)d_in[1];
    const int*   p_mask  = (const int*)d_in[2];
    const int*   c_mask  = (const int*)d_in[3];
    const float* ln_p_w  = (const float*)d_in[4];
    const float* ln_p_b  = (const float*)d_in[5];
    const float* ln_c_w  = (const float*)d_in[6];
    const float* ln_c_b  = (const float*)d_in[7];
    const float* W_p     = (const float*)d_in[8];
    const float* b_p     = (const float*)d_in[9];
    const float* W_c     = (const float*)d_in[10];
    const float* b_c     = (const float*)d_in[11];
    const float* W_out   = (const float*)d_in[12];
    const float* b_out   = (const float*)d_in[13];
    float* out = (float*)d_out;

    ln_linear_all<<<LP + LC, 128>>>(p_embed, c_embed, ln_p_w, ln_p_b,
                                    ln_c_w, ln_c_b, W_p, b_p, W_c, b_c);

    dim3 gB(LC / 8, HID / 2);
    make_M_kernel<<<gB, 128>>>(W_out);

    long long main_elems = (long long)LP * LC * PAIR;
    int has_mask = ((long long)out_size >= main_elems + (long long)LP * LC) ? 1 : 0;
    float* outm = out + main_elems;

    dim3 gC(LP / TILE_I, LC / JPB);
    pair_kernel<<<gC, 256>>>(b_out, p_mask, c_mask, out, outm, has_mask);
}